// round 14
// baseline (speedup 1.0000x reference)
#include <cuda_runtime.h>
#include <cuda_fp16.h>
#include <cstdint>

// Problem constants
#define AA   128
#define SPN  1024
#define FF   128
#define HH   4
#define DD   128
#define NNW  512
#define RR   131072

// ------------------------------------------------------------------
// Scratch (static device globals — allocation-rule safe)
// ------------------------------------------------------------------
__device__ __align__(16) __half g_wth[NNW * FF];                      // W_r^T fp16: [n_g][f]
__device__ __align__(16) float g_sl[RR * HH];
__device__ __align__(16) float g_sr[RR * HH];
__device__ __align__(16) float g_ul[FF * HH];
__device__ __align__(16) float g_ur[FF * HH];

// ------------------------------------------------------------------
// PTX helpers (sm_80-level: ldmatrix + mma.sync + cp.async — valid on plain sm_103)
// ------------------------------------------------------------------
__device__ __forceinline__ uint32_t smem_u32(const void* p) {
    uint32_t a;
    asm("{ .reg .u64 t; cvta.to.shared.u64 t, %1; cvt.u32.u64 %0, t; }" : "=r"(a) : "l"(p));
    return a;
}
__device__ __forceinline__ void ldsm4(uint32_t* r, uint32_t addr) {
    asm volatile("ldmatrix.sync.aligned.m8n8.x4.shared.b16 {%0,%1,%2,%3}, [%4];"
                 : "=r"(r[0]), "=r"(r[1]), "=r"(r[2]), "=r"(r[3]) : "r"(addr));
}
__device__ __forceinline__ void ldsm2(uint32_t* r, uint32_t addr) {
    asm volatile("ldmatrix.sync.aligned.m8n8.x2.shared.b16 {%0,%1}, [%2];"
                 : "=r"(r[0]), "=r"(r[1]) : "r"(addr));
}
__device__ __forceinline__ void mma16816(float* c, const uint32_t* a, const uint32_t* b) {
    asm volatile("mma.sync.aligned.m16n8k16.row.col.f32.f16.f16.f32 "
                 "{%0,%1,%2,%3}, {%4,%5,%6,%7}, {%8,%9}, {%0,%1,%2,%3};"
                 : "+f"(c[0]), "+f"(c[1]), "+f"(c[2]), "+f"(c[3])
                 : "r"(a[0]), "r"(a[1]), "r"(a[2]), "r"(a[3]), "r"(b[0]), "r"(b[1]));
}
__device__ __forceinline__ void cpasync16(uint32_t dst, const void* src) {
    asm volatile("cp.async.cg.shared.global [%0], [%1], 16;" :: "r"(dst), "l"(src));
}
__device__ __forceinline__ void cpcommit() { asm volatile("cp.async.commit_group;"); }
template<int N> __device__ __forceinline__ void cpwait() {
    asm volatile("cp.async.wait_group %0;" :: "n"(N));
}
__device__ __forceinline__ uint32_t h2_u32(__half2 v) {
    return *reinterpret_cast<uint32_t*>(&v);
}

// ============================================================
// K1: fold w_attn into W_l / W_r per head
// ============================================================
__global__ void k_u(const float* __restrict__ Wl, const float* __restrict__ Wr,
                    const float* __restrict__ wa) {
    __shared__ float w[2 * DD];
    int t = threadIdx.x;               // 512 threads
    if (t < 2 * DD) w[t] = wa[t];
    __syncthreads();
    int f = t >> 2, hh = t & 3;
    const float* pl = Wl + (size_t)f * NNW + hh * DD;
    const float* pr = Wr + (size_t)f * NNW + hh * DD;
    float sl = 0.f, sr = 0.f;
#pragma unroll 4
    for (int d = 0; d < DD; d++) {
        sl = fmaf(pl[d], w[d], sl);
        sr = fmaf(pr[d], w[DD + d], sr);
    }
    g_ul[f * HH + hh] = sl;
    g_ur[f * HH + hh] = sr;
}

// ============================================================
// K2: s_l / s_r  (one warp per row) — exact fp32
// ============================================================
__global__ void __launch_bounds__(256) k_s(const float* __restrict__ h) {
    __shared__ float ul[FF * HH], ur[FF * HH];
    int t = threadIdx.x;
    for (int q = t; q < FF * HH; q += 256) { ul[q] = g_ul[q]; ur[q] = g_ur[q]; }
    __syncthreads();
    int warp = t >> 5, lane = t & 31;
    int rid = blockIdx.x * 8 + warp;
    int sp = rid >> 7, a = rid & 127;
    const float* hr = h + ((size_t)a * SPN + sp) * FF;
    float hv[4];
#pragma unroll
    for (int u = 0; u < 4; u++) hv[u] = hr[lane + 32 * u];
    float accl[4] = {0, 0, 0, 0}, accr[4] = {0, 0, 0, 0};
#pragma unroll
    for (int u = 0; u < 4; u++) {
        int f = lane + 32 * u;
#pragma unroll
        for (int hh = 0; hh < 4; hh++) {
            accl[hh] = fmaf(hv[u], ul[f * 4 + hh], accl[hh]);
            accr[hh] = fmaf(hv[u], ur[f * 4 + hh], accr[hh]);
        }
    }
#pragma unroll
    for (int hh = 0; hh < 4; hh++) {
        for (int o = 16; o; o >>= 1) {
            accl[hh] += __shfl_xor_sync(0xffffffffu, accl[hh], o);
            accr[hh] += __shfl_xor_sync(0xffffffffu, accr[hh], o);
        }
    }
    if (lane == 0) {
        *(float4*)&g_sl[rid * 4] = make_float4(accl[0], accl[1], accl[2], accl[3]);
        *(float4*)&g_sr[rid * 4] = make_float4(accr[0], accr[1], accr[2], accr[3]);
    }
}

// ============================================================
// K3: transpose W_r to fp16: g_wth[n][f] = fp16(W_r[f][n])
// ============================================================
__global__ void __launch_bounds__(256) k_split_w(const float* __restrict__ Wr) {
    int t = blockIdx.x * 256 + threadIdx.x;            // < NNW*FF = 65536
    int f = t & 127, n = t >> 7;
    g_wth[t] = __float2half_rn(Wr[(size_t)f * NNW + n]);
}

// ============================================================
// K4: FUSED per-sp kernel (512 threads):
//   fill h-tile fp16 (once, reused by 4 heads)
//   2 softmax passes (pass0: exact fp32 'a' -> out2 + fp16 planes h0,h1;
//                     pass1: recompute, planes h2,h3)
//   per head: cp.async W_h -> MMA1 (g in SMEM, never DRAM) -> MMA2 accum.
// ============================================================
// SMEM (all tile planes [128 rows][136 halves], stride 272B):
#define F_A0   0
#define F_A1   34816
#define F_HT   69632
#define F_WT   104448
#define F_GT   139264
#define F_SIZE 174080

// cp.async fill of a [128][128]-half tile into 272B-stride smem (512 thr)
__device__ __forceinline__ void fill_w_tile(uint32_t dbuf, const __half* src, int tid) {
#pragma unroll
    for (int q = 0; q < 4; q++) {
        int idx = tid + q * 512;          // 0..2047
        int r = idx >> 4, c = idx & 15;   // 128 rows x 16 chunks of 16B
        cpasync16(dbuf + (uint32_t)(r * 272 + c * 16), src + r * 128 + c * 8);
    }
    cpcommit();
}

__global__ void __launch_bounds__(512) k_fused(const float* __restrict__ h,
                                               float* __restrict__ out1,
                                               float* __restrict__ out2) {
    extern __shared__ char smem[];
    uint32_t sb = smem_u32(smem);
    int tid = threadIdx.x;
    int lane = tid & 31, wid = tid >> 5;      // 16 warps
    int wm = wid & 3, wn = wid >> 2;          // warp tile 32 x 32
    int sp = blockIdx.x;

    // prefetch W head 0
    fill_w_tile(sb + F_WT, g_wth, tid);

    // fill h tile: fp32 global (strided rows) -> fp16 smem [a][f]
    for (int idx = tid; idx < 4096; idx += 512) {     // 128 rows x 32 float4
        int row = idx >> 5, c = idx & 31;
        float4 v = *(const float4*)&h[((size_t)row * SPN + sp) * FF + c * 4];
        uint32_t off = F_HT + (uint32_t)(row * 136 + c * 4) * 2;
        *(uint32_t*)(smem + off) = h2_u32(__floats2half2_rn(v.x, v.y));
        *(uint32_t*)(smem + off + 4) = h2_u32(__floats2half2_rn(v.z, v.w));
    }

    float acc2[2][4][4];
#pragma unroll
    for (int i = 0; i < 2; i++)
#pragma unroll
        for (int j = 0; j < 4; j++)
#pragma unroll
            for (int q = 0; q < 4; q++) acc2[i][j][q] = 0.f;

    for (int sel = 0; sel < 2; sel++) {
        // ---- softmax pass: all 4 heads in regs; park heads 2*sel, 2*sel+1 ----
        {
            float4 slj[4];
#pragma unroll
            for (int u = 0; u < 4; u++)
                slj[u] = *(const float4*)&g_sl[(sp * 128 + lane + 32 * u) * 4];

            for (int it = 0; it < 8; it++) {
                int i = it * 16 + wid;
                float4 sri = *(const float4*)&g_sr[(sp * 128 + i) * 4];
                float e[4][4];
#pragma unroll
                for (int u = 0; u < 4; u++) {
                    int j = lane + 32 * u;
                    float v[4] = {sri.x + slj[u].x, sri.y + slj[u].y,
                                  sri.z + slj[u].z, sri.w + slj[u].w};
#pragma unroll
                    for (int hh = 0; hh < 4; hh++) {
                        float x = v[hh];
                        x = (x >= 0.f) ? x : 0.2f * x;
                        e[u][hh] = (j == i) ? -3.0e38f : x;
                    }
                }
#pragma unroll
                for (int hh = 0; hh < 4; hh++) {
                    float m = fmaxf(fmaxf(e[0][hh], e[1][hh]), fmaxf(e[2][hh], e[3][hh]));
                    for (int o = 16; o; o >>= 1) m = fmaxf(m, __shfl_xor_sync(0xffffffffu, m, o));
                    float s = 0.f;
#pragma unroll
                    for (int u = 0; u < 4; u++) {
                        int j = lane + 32 * u;
                        float p = (j == i) ? 0.f : __expf(e[u][hh] - m);
                        e[u][hh] = p;
                        s += p;
                    }
                    for (int o = 16; o; o >>= 1) s += __shfl_xor_sync(0xffffffffu, s, o);
                    float inv = 1.0f / s;
#pragma unroll
                    for (int u = 0; u < 4; u++) e[u][hh] *= inv;
                }
                if (sel == 0) {   // exact fp32 'a', coalesced float4
                    float* base = out2 + (size_t)sp * 65536 + (size_t)i * 512;
#pragma unroll
                    for (int u = 0; u < 4; u++) {
                        int j = lane + 32 * u;
                        *(float4*)&base[j * 4] = make_float4(e[u][0], e[u][1], e[u][2], e[u][3]);
                    }
                }
                // park this pass's two heads as fp16 planes
#pragma unroll
                for (int k2 = 0; k2 < 2; k2++) {
                    int hh = sel * 2 + k2;
                    uint32_t pb = (k2 ? F_A1 : F_A0) + (uint32_t)(i * 136) * 2;
#pragma unroll
                    for (int u = 0; u < 4; u++) {
                        int j = lane + 32 * u;
                        *(__half*)(smem + pb + j * 2) = __float2half_rn(e[u][hh]);
                    }
                }
            }
        }
        __syncthreads();   // planes + (sel==0: h tile) visible to all

        for (int k2 = 0; k2 < 2; k2++) {
            int hh = sel * 2 + k2;
            cpwait<0>();
            __syncthreads();   // W_hh visible to all warps

            // ---- MMA1: g_h[n][a] = W_h @ h^T ----
            float acc1[2][4][4];
#pragma unroll
            for (int i = 0; i < 2; i++)
#pragma unroll
                for (int j = 0; j < 4; j++)
#pragma unroll
                    for (int q = 0; q < 4; q++) acc1[i][j][q] = 0.f;
#pragma unroll
            for (int ks = 0; ks < 8; ks++) {
                int kb = ks * 16;
                uint32_t bh[4][2];
                int bko = kb + ((lane >> 3) & 1) * 8;
#pragma unroll
                for (int nt = 0; nt < 4; nt++) {
                    uint32_t boff = (uint32_t)((wn * 32 + nt * 8 + (lane & 7)) * 136 + bko) * 2;
                    ldsm2(bh[nt], sb + F_HT + boff);
                }
                int ako = kb + (lane >> 4) * 8;
#pragma unroll
                for (int mt = 0; mt < 2; mt++) {
                    uint32_t aoff = (uint32_t)((wm * 32 + mt * 16 + (lane & 15)) * 136 + ako) * 2;
                    uint32_t ah[4];
                    ldsm4(ah, sb + F_WT + aoff);
#pragma unroll
                    for (int nt = 0; nt < 4; nt++) mma16816(acc1[mt][nt], ah, bh[nt]);
                }
            }
            // store g to SMEM fp16 [d][j] (d = n_g local, j = a)
#pragma unroll
            for (int mt = 0; mt < 2; mt++) {
#pragma unroll
                for (int nt = 0; nt < 4; nt++) {
                    int gm = wm * 32 + mt * 16 + (lane >> 2);
                    int col = wn * 32 + nt * 8 + (lane & 3) * 2;
                    *(__half2*)(smem + F_GT + (uint32_t)(gm * 136 + col) * 2) =
                        __floats2half2_rn(acc1[mt][nt][0], acc1[mt][nt][1]);
                    *(__half2*)(smem + F_GT + (uint32_t)((gm + 8) * 136 + col) * 2) =
                        __floats2half2_rn(acc1[mt][nt][2], acc1[mt][nt][3]);
                }
            }
            __syncthreads();   // g complete; W buffer free

            if (hh < 3) fill_w_tile(sb + F_WT, g_wth + (hh + 1) * 16384, tid);

            // ---- MMA2: acc2[i][d] += a_hh @ g_h^T ----
            uint32_t aplane = k2 ? F_A1 : F_A0;
#pragma unroll
            for (int ks = 0; ks < 8; ks++) {
                int kb = ks * 16;
                uint32_t bh[4][2];
                int bko = kb + ((lane >> 3) & 1) * 8;
#pragma unroll
                for (int nt = 0; nt < 4; nt++) {
                    uint32_t boff = (uint32_t)((wn * 32 + nt * 8 + (lane & 7)) * 136 + bko) * 2;
                    ldsm2(bh[nt], sb + F_GT + boff);
                }
                int ako = kb + (lane >> 4) * 8;
#pragma unroll
                for (int mt = 0; mt < 2; mt++) {
                    uint32_t aoff = (uint32_t)((wm * 32 + mt * 16 + (lane & 15)) * 136 + ako) * 2;
                    uint32_t af[4];
                    ldsm4(af, sb + aplane + aoff);
#pragma unroll
                    for (int nt = 0; nt < 4; nt++) mma16816(acc2[mt][nt], af, bh[nt]);
                }
            }
            __syncthreads();   // done reading g + planes before they are overwritten
        }
    }

    // epilogue: x0.25, output layout (A, S, P, D)
#pragma unroll
    for (int mt = 0; mt < 2; mt++) {
#pragma unroll
        for (int nt = 0; nt < 4; nt++) {
            int i0 = wm * 32 + mt * 16 + (lane >> 2);
            int d0 = wn * 32 + nt * 8 + (lane & 3) * 2;
            float2 v0 = make_float2(acc2[mt][nt][0] * 0.25f, acc2[mt][nt][1] * 0.25f);
            float2 v1 = make_float2(acc2[mt][nt][2] * 0.25f, acc2[mt][nt][3] * 0.25f);
            *(float2*)&out1[((size_t)i0 * SPN + sp) * 128 + d0] = v0;
            *(float2*)&out1[((size_t)(i0 + 8) * SPN + sp) * 128 + d0] = v1;
        }
    }
}

// ============================================================
extern "C" void kernel_launch(void* const* d_in, const int* in_sizes, int n_in,
                              void* d_out, int out_size) {
    const float* h  = (const float*)d_in[0];
    const float* Wl = (const float*)d_in[1];
    const float* Wr = (const float*)d_in[2];
    const float* wa = (const float*)d_in[3];

    float* out1 = (float*)d_out;                 // attn_res: A*S*P*D
    float* out2 = out1 + (size_t)AA * SPN * DD;  // a: S*P*A*A*H

    // Unconditional (no static guards): immediate, idempotent, capture-safe.
    cudaFuncSetAttribute(k_fused, cudaFuncAttributeMaxDynamicSharedMemorySize, F_SIZE);

    k_u<<<1, 512>>>(Wl, Wr, wa);
    k_s<<<RR / 8, 256>>>(h);
    k_split_w<<<(NNW * FF) / 256, 256>>>(Wr);
    k_fused<<<SPN, 512, F_SIZE>>>(h, out1, out2);
}